// round 15
// baseline (speedup 1.0000x reference)
#include <cuda_runtime.h>
#include <cuda_fp16.h>
#include <math.h>

// ---------------------------------------------------------------------------
// GATNet: 4x GATConv + pool + MLP head.
// R15: agg8 epilogue fused with the NEXT layer's transform (warp-internal
// shuffle GEMV, W staged in smem).  Removes t2/t3 kernels entirely.
// Ping-pong feature/logit buffers A<->B.  PDL retained on the chain.
// ---------------------------------------------------------------------------

#define NNODES 20000
#define E0     320000
#define ETOT   (E0 + NNODES)
#define NG     8
#define SCAN_T 1024
#define SCAN_CHUNK ((NNODES + SCAN_T - 1) / SCAN_T)

__device__ __align__(16) float  g_featA[NNODES * 64];   // post-ELU feats (L3 out, L4 out)
__device__ __align__(16) __half g_ftA  [NNODES * 64];   // transformed feats, buffer A
__device__ __align__(16) __half g_ftB  [NNODES * 64];   // transformed feats, buffer B
__device__ __align__(16) __half g_ft4  [NNODES * 256];  // L4 feats, [pair32][head4] half2
__device__ __align__(16) float  g_asA  [NNODES * 8];
__device__ __align__(16) float  g_adA  [NNODES * 8];
__device__ __align__(16) float  g_asB  [NNODES * 8];
__device__ __align__(16) float  g_adB  [NNODES * 8];
__device__ int g_cnt[NNODES];
__device__ int g_rowstart[NNODES + 1];
__device__ int g_cursor[NNODES];
__device__ int g_col[ETOT];

__device__ __forceinline__ float leaky02(float v) { return fmaxf(v, 0.2f * v); }
__device__ __forceinline__ float eluf(float v)    { return v > 0.f ? v : (__expf(v) - 1.f); }
__device__ __forceinline__ void gdep_sync() {
#if __CUDA_ARCH__ >= 900
    cudaGridDependencySynchronize();
#endif
}

// ---------------------------------------------------------------------------
// CSR build: 4 edges per thread.
// ---------------------------------------------------------------------------
#define CSR_BLKS 334
#define CSR_STRIDE (CSR_BLKS * 256)

__global__ void k_count(const int* __restrict__ ei) {
    int gtid = blockIdx.x * blockDim.x + threadIdx.x;
    int dd[4]; bool ok[4];
#pragma unroll
    for (int k = 0; k < 4; k++) {
        int e = gtid + k * CSR_STRIDE;
        ok[k] = (e < ETOT);
        dd[k] = ok[k] ? ((e < E0) ? ei[E0 + e] : (e - E0)) : 0;
    }
#pragma unroll
    for (int k = 0; k < 4; k++)
        if (ok[k]) atomicAdd(&g_cnt[dd[k]], 1);
}
__global__ void k_scan() {
    __shared__ int sp[SCAN_T];
    int t = threadIdx.x;
    int b0 = t * SCAN_CHUNK;
    int b1 = min(b0 + SCAN_CHUNK, NNODES);
    int sum = 0;
    for (int i = b0; i < b1; i++) sum += g_cnt[i];
    sp[t] = sum;
    __syncthreads();
    for (int off = 1; off < SCAN_T; off <<= 1) {
        int v = (t >= off) ? sp[t - off] : 0;
        __syncthreads();
        sp[t] += v;
        __syncthreads();
    }
    int base = (t == 0) ? 0 : sp[t - 1];
    for (int i = b0; i < b1; i++) {
        g_rowstart[i] = base;
        g_cursor[i]   = base;
        base += g_cnt[i];
    }
    if (t == SCAN_T - 1) g_rowstart[NNODES] = base;
}
__global__ void k_fill(const int* __restrict__ ei) {
    int gtid = blockIdx.x * blockDim.x + threadIdx.x;
    if (gtid < NNODES) g_cnt[gtid] = 0;
    int ss[4], dd[4]; bool ok[4];
#pragma unroll
    for (int k = 0; k < 4; k++) {
        int e = gtid + k * CSR_STRIDE;
        ok[k] = (e < ETOT);
        if (ok[k]) {
            if (e < E0) { ss[k] = ei[e]; dd[k] = ei[E0 + e]; }
            else        { ss[k] = e - E0; dd[k] = e - E0; }
        }
    }
#pragma unroll
    for (int k = 0; k < 4; k++) {
        if (ok[k]) {
            int pos = atomicAdd(&g_cursor[dd[k]], 1);
            g_col[pos] = ss[k];
        }
    }
}

// ---------------------------------------------------------------------------
// Layer-1 transform: ftA = x@W1, logits asA/adA.  16 nodes/block.
// ---------------------------------------------------------------------------
__global__ void k_transform1(const float* __restrict__ xin,
                             const float* __restrict__ W,
                             const float* __restrict__ a_src,
                             const float* __restrict__ a_dst) {
    constexpr int IN = 16, D = 64, H = 8, C = 8, NPB = 16;
    __shared__ __align__(16) float sW[IN * D];
    __shared__ __align__(16) float sx[NPB][IN];
    __shared__ __align__(16) float sh[NPB][D];
    const int t  = threadIdx.x;
    const int li = t / 16;
    const int q  = t % 16;

    for (int i = t; i < IN * D / 4; i += 256)
        ((float4*)sW)[i] = ((const float4*)W)[i];

    const int tile = blockIdx.x;               // grid = 1250
    for (int i = t; i < NPB * IN; i += 256) {
        int nn = tile * NPB + i / IN;
        sx[i / IN][i % IN] = xin[nn * IN + i % IN];
    }
    __syncthreads();

    const int n = tile * NPB + li;
    float4 acc = make_float4(0.f, 0.f, 0.f, 0.f);
#pragma unroll
    for (int i = 0; i < IN; i++) {
        float xv = sx[li][i];
        float4 w4 = *(const float4*)&sW[i * D + 4 * q];
        acc.x += xv * w4.x; acc.y += xv * w4.y;
        acc.z += xv * w4.z; acc.w += xv * w4.w;
    }
    {
        __half2* dst = (__half2*)&g_ftA[n * D + 4 * q];
        dst[0] = __floats2half2_rn(acc.x, acc.y);
        dst[1] = __floats2half2_rn(acc.z, acc.w);
        *(float4*)&sh[li][4 * q] = acc;
    }
    __syncthreads();

    if (t < NPB * H) {
        int ln = t / H, h = t % H;
        int nn = tile * NPB + ln;
        float as = 0.f, ad = 0.f;
#pragma unroll
        for (int c = 0; c < C; c++) {
            float hv = sh[ln][h * C + c];
            as += hv * a_src[h * C + c];
            ad += hv * a_dst[h * C + c];
        }
        g_asA[nn * H + h] = as;
        g_adA[nn * H + h] = ad;
    }
}

// ---------------------------------------------------------------------------
// FUSED agg8 + next-layer transform.  4 nodes/warp, lane = 8*ni + h.
// Edge loop: softmax-aggregate current layer (reads ping buffers).
// Epilogue: o = elu(agg+bias); h_next = o @ Wn via warp-shuffle GEMV
// (Wn staged in 16KB smem); next logits purely lane-local.
// FLIP=false: read A, write B.  FLIP=true: read B, write A.
// grid MUST be exactly NNODES/4/8 blocks (no bounds check).
// ---------------------------------------------------------------------------
template<bool FLIP, bool PDL>
__global__ void __launch_bounds__(256)
k_agg8f(const float* __restrict__ bias,
        const float* __restrict__ Wn,
        const float* __restrict__ asn,
        const float* __restrict__ adn) {
    __shared__ __align__(16) float sW[64 * 64];
    const int t    = threadIdx.x;
    const int lane = t & 31;
    const int gw   = (blockIdx.x * 256 + t) >> 5;
    const int h    = lane & 7;
    const int d    = 4 * gw + (lane >> 3);

    const __half* __restrict__ ftin = FLIP ? g_ftB : g_ftA;
    const float*  __restrict__ asin_ = FLIP ? g_asB : g_asA;
    const float*  __restrict__ adin_ = FLIP ? g_adB : g_adA;
    __half* __restrict__ ftout = FLIP ? g_ftA : g_ftB;
    float*  __restrict__ asout = FLIP ? g_asA : g_asB;
    float*  __restrict__ adout = FLIP ? g_adA : g_adB;

    // PDL prologue: stage next-layer W + per-lane vectors (inputs only)
    for (int i = t; i < 1024; i += 256)
        ((float4*)sW)[i] = ((const float4*)Wn)[i];
    float4 b0  = *(const float4*)&bias[8 * h];
    float4 b1  = *(const float4*)&bias[8 * h + 4];
    float4 wa0 = *(const float4*)&asn[8 * h];
    float4 wa1 = *(const float4*)&asn[8 * h + 4];
    float4 wd0 = *(const float4*)&adn[8 * h];
    float4 wd1 = *(const float4*)&adn[8 * h + 4];

    if (PDL) gdep_sync();
    __syncthreads();

    const float adv = adin_[d * 8 + h];
    const int r0 = g_rowstart[d];
    const int r1 = g_rowstart[d + 1];
    const uint4* __restrict__ ftp = (const uint4*)ftin;

    float den = 0.f;
    float a0 = 0.f, a1 = 0.f, a2 = 0.f, a3 = 0.f;
    float a4 = 0.f, a5 = 0.f, a6 = 0.f, a7 = 0.f;
#pragma unroll 4
    for (int j = r0; j < r1; j++) {
        int s = g_col[j];
        float e = __expf(leaky02(asin_[s * 8 + h] + adv));
        den += e;
        uint4 raw = __ldg(&ftp[s * 8 + h]);
        float2 f0 = __half22float2(*(const __half2*)&raw.x);
        float2 f1 = __half22float2(*(const __half2*)&raw.y);
        float2 f2 = __half22float2(*(const __half2*)&raw.z);
        float2 f3 = __half22float2(*(const __half2*)&raw.w);
        a0 += e * f0.x; a1 += e * f0.y;
        a2 += e * f1.x; a3 += e * f1.y;
        a4 += e * f2.x; a5 += e * f2.y;
        a6 += e * f3.x; a7 += e * f3.y;
    }
    float inv = 1.f / den;
    float o[8];
    o[0] = eluf(a0 * inv + b0.x);
    o[1] = eluf(a1 * inv + b0.y);
    o[2] = eluf(a2 * inv + b0.z);
    o[3] = eluf(a3 * inv + b0.w);
    o[4] = eluf(a4 * inv + b1.x);
    o[5] = eluf(a5 * inv + b1.y);
    o[6] = eluf(a6 * inv + b1.z);
    o[7] = eluf(a7 * inv + b1.w);

    // ---- next-layer transform: warp-shuffle GEMV ----
    float4 c0 = make_float4(0.f, 0.f, 0.f, 0.f);
    float4 c1 = make_float4(0.f, 0.f, 0.f, 0.f);
    const int lbase = lane & 24;
#pragma unroll
    for (int kk = 0; kk < 64; kk++) {
        float xk = __shfl_sync(0xffffffffu, o[kk & 7], lbase | (kk >> 3), 32);
        float4 w0 = *(const float4*)&sW[kk * 64 + 8 * h];
        float4 w1 = *(const float4*)&sW[kk * 64 + 8 * h + 4];
        c0.x += xk * w0.x; c0.y += xk * w0.y;
        c0.z += xk * w0.z; c0.w += xk * w0.w;
        c1.x += xk * w1.x; c1.y += xk * w1.y;
        c1.z += xk * w1.z; c1.w += xk * w1.w;
    }
    // store transformed feats (fp16, agg8 gather layout)
    {
        __half2 p0 = __floats2half2_rn(c0.x, c0.y);
        __half2 p1 = __floats2half2_rn(c0.z, c0.w);
        __half2 p2 = __floats2half2_rn(c1.x, c1.y);
        __half2 p3 = __floats2half2_rn(c1.z, c1.w);
        __half2* dst = (__half2*)&ftout[d * 64 + 8 * h];
        dst[0] = p0; dst[1] = p1; dst[2] = p2; dst[3] = p3;
    }
    // next-layer logits (lane-local: channels 8h..8h+7 = head h)
    float pas = c0.x * wa0.x + c0.y * wa0.y + c0.z * wa0.z + c0.w * wa0.w
              + c1.x * wa1.x + c1.y * wa1.y + c1.z * wa1.z + c1.w * wa1.w;
    float pad = c0.x * wd0.x + c0.y * wd0.y + c0.z * wd0.z + c0.w * wd0.w
              + c1.x * wd1.x + c1.y * wd1.y + c1.z * wd1.z + c1.w * wd1.w;
    asout[d * 8 + h] = pas;
    adout[d * 8 + h] = pad;
}

// ---------------------------------------------------------------------------
// Plain agg8 (layer 3): reads buffer A, writes g_featA (input to t4).
// ---------------------------------------------------------------------------
__global__ void k_agg8(const float* __restrict__ bias) {
    int gw   = (blockIdx.x * blockDim.x + threadIdx.x) >> 5;
    int lane = threadIdx.x & 31;
    const int h = lane & 7;
    const int d = 4 * gw + (lane >> 3);
    float4 b0 = *(const float4*)&bias[8 * h];
    float4 b1 = *(const float4*)&bias[8 * h + 4];

    gdep_sync();

    const float adv = g_adA[d * 8 + h];
    const int r0 = g_rowstart[d];
    const int r1 = g_rowstart[d + 1];
    const uint4* __restrict__ ftp = (const uint4*)g_ftA;

    float den = 0.f;
    float a0 = 0.f, a1 = 0.f, a2 = 0.f, a3 = 0.f;
    float a4 = 0.f, a5 = 0.f, a6 = 0.f, a7 = 0.f;
#pragma unroll 4
    for (int j = r0; j < r1; j++) {
        int s = g_col[j];
        float e = __expf(leaky02(g_asA[s * 8 + h] + adv));
        den += e;
        uint4 raw = __ldg(&ftp[s * 8 + h]);
        float2 f0 = __half22float2(*(const __half2*)&raw.x);
        float2 f1 = __half22float2(*(const __half2*)&raw.y);
        float2 f2 = __half22float2(*(const __half2*)&raw.z);
        float2 f3 = __half22float2(*(const __half2*)&raw.w);
        a0 += e * f0.x; a1 += e * f0.y;
        a2 += e * f1.x; a3 += e * f1.y;
        a4 += e * f2.x; a5 += e * f2.y;
        a6 += e * f3.x; a7 += e * f3.y;
    }
    float inv = 1.f / den;
    float4 o0, o1;
    o0.x = eluf(a0 * inv + b0.x);
    o0.y = eluf(a1 * inv + b0.y);
    o0.z = eluf(a2 * inv + b0.z);
    o0.w = eluf(a3 * inv + b0.w);
    o1.x = eluf(a4 * inv + b1.x);
    o1.y = eluf(a5 * inv + b1.y);
    o1.z = eluf(a6 * inv + b1.z);
    o1.w = eluf(a7 * inv + b1.w);
    *(float4*)&g_featA[d * 64 + 8 * h]     = o0;
    *(float4*)&g_featA[d * 64 + 8 * h + 4] = o1;
}

// ---------------------------------------------------------------------------
// Layer-4 transform (64 -> 256): 16 nodes/tile, 4 nodes/thread.
// Head-interleaved output; logits into g_asA/g_adA (stride 4).
// ---------------------------------------------------------------------------
__global__ void k_transform4(const float* __restrict__ W,
                             const float* __restrict__ a_src,
                             const float* __restrict__ a_dst) {
    constexpr int NPB = 16;
    __shared__ __align__(16) float sx[NPB][64];
    __shared__ __align__(16) float sh[NPB][256];
    const int t = threadIdx.x;
    const int q = t & 63;
    const int m = t >> 6;
    const int h  = q >> 4;
    const int p0 = (2 * q) & 31;
    __half2* __restrict__ f4 = (__half2*)g_ft4;

    gdep_sync();

    const int tile = blockIdx.x;                   // grid = 1250
    for (int i = t; i < NPB * 64; i += 256) {
        int nn = tile * NPB + (i >> 6);
        sx[i >> 6][i & 63] = g_featA[nn * 64 + (i & 63)];
    }
    __syncthreads();

    float4 acc0 = make_float4(0.f,0.f,0.f,0.f);
    float4 acc1 = make_float4(0.f,0.f,0.f,0.f);
    float4 acc2 = make_float4(0.f,0.f,0.f,0.f);
    float4 acc3 = make_float4(0.f,0.f,0.f,0.f);
#pragma unroll 4
    for (int k = 0; k < 64; k++) {
        float4 w4 = __ldg((const float4*)&W[k * 256 + 4 * q]);
        float x0 = sx[m * 4 + 0][k];
        float x1 = sx[m * 4 + 1][k];
        float x2 = sx[m * 4 + 2][k];
        float x3 = sx[m * 4 + 3][k];
        acc0.x += x0*w4.x; acc0.y += x0*w4.y; acc0.z += x0*w4.z; acc0.w += x0*w4.w;
        acc1.x += x1*w4.x; acc1.y += x1*w4.y; acc1.z += x1*w4.z; acc1.w += x1*w4.w;
        acc2.x += x2*w4.x; acc2.y += x2*w4.y; acc2.z += x2*w4.z; acc2.w += x2*w4.w;
        acc3.x += x3*w4.x; acc3.y += x3*w4.y; acc3.z += x3*w4.z; acc3.w += x3*w4.w;
    }
    float4 accs[4] = {acc0, acc1, acc2, acc3};
#pragma unroll
    for (int i = 0; i < 4; i++) {
        int nl = m * 4 + i;
        int n  = tile * NPB + nl;
        f4[n * 128 + p0 * 4 + h]       = __floats2half2_rn(accs[i].x, accs[i].y);
        f4[n * 128 + (p0 + 1) * 4 + h] = __floats2half2_rn(accs[i].z, accs[i].w);
        *(float4*)&sh[nl][4 * q] = accs[i];
    }
    __syncthreads();

    if (t < NPB * 4) {
        int nl = t >> 2, hh = t & 3;
        int nn = tile * NPB + nl;
        float as = 0.f, ad = 0.f;
#pragma unroll 8
        for (int c = 0; c < 64; c++) {
            float hv = sh[nl][hh * 64 + c];
            as += hv * a_src[hh * 64 + c];
            ad += hv * a_dst[hh * 64 + c];
        }
        g_asA[nn * 4 + hh] = as;
        g_adA[nn * 4 + hh] = ad;
    }
}

// ---------------------------------------------------------------------------
// Layer-4 aggregation.  Warp per node; one 16B gather = all 4 heads.
// ---------------------------------------------------------------------------
__global__ void k_agg4(const float* __restrict__ bias) {
    int wid  = (blockIdx.x * blockDim.x + threadIdx.x) >> 5;
    int lane = threadIdx.x & 31;
    const int hm = lane & 3;
    float2 b = *(const float2*)&bias[2 * lane];

    gdep_sync();
    if (wid >= NNODES) return;
    const int d  = wid;
    const float adv_m = g_adA[d * 4 + hm];
    const int r0 = g_rowstart[d];
    const int r1 = g_rowstart[d + 1];
    const uint4* __restrict__ ftp = (const uint4*)g_ft4;

    float den[4] = {0.f, 0.f, 0.f, 0.f};
    float ax[4]  = {0.f, 0.f, 0.f, 0.f};
    float ay[4]  = {0.f, 0.f, 0.f, 0.f};
#pragma unroll 4
    for (int j = r0; j < r1; j++) {
        int s = g_col[j];
        float em = __expf(leaky02(g_asA[s * 4 + hm] + adv_m));
        float ev0 = __shfl_sync(0xffffffff, em, 0, 4);
        float ev1 = __shfl_sync(0xffffffff, em, 1, 4);
        float ev2 = __shfl_sync(0xffffffff, em, 2, 4);
        float ev3 = __shfl_sync(0xffffffff, em, 3, 4);
        uint4 raw = __ldg(&ftp[s * 32 + lane]);
        float2 f0 = __half22float2(*(const __half2*)&raw.x);
        float2 f1 = __half22float2(*(const __half2*)&raw.y);
        float2 f2 = __half22float2(*(const __half2*)&raw.z);
        float2 f3 = __half22float2(*(const __half2*)&raw.w);
        den[0] += ev0; ax[0] += ev0 * f0.x; ay[0] += ev0 * f0.y;
        den[1] += ev1; ax[1] += ev1 * f1.x; ay[1] += ev1 * f1.y;
        den[2] += ev2; ax[2] += ev2 * f2.x; ay[2] += ev2 * f2.y;
        den[3] += ev3; ax[3] += ev3 * f3.x; ay[3] += ev3 * f3.y;
    }
    float v1 = 0.f, v2 = 0.f;
#pragma unroll
    for (int hh = 0; hh < 4; hh++) {
        float inv = 1.f / den[hh];
        v1 += ax[hh] * inv;
        v2 += ay[hh] * inv;
    }
    float2 o;
    o.x = eluf(0.25f * v1 + b.x);
    o.y = eluf(0.25f * v2 + b.y);
    *(float2*)&g_featA[d * 64 + 2 * lane] = o;
}

// ---------------------------------------------------------------------------
// Fused pool+head (8 blocks).
// ---------------------------------------------------------------------------
__global__ void k_poolhead(const int* __restrict__ fidx, const int* __restrict__ flag,
                           int nf,
                           const int* __restrict__ dvi,
                           const float* __restrict__ Wp,
                           const float* __restrict__ Wt,
                           const float* __restrict__ Wo,
                           const float* __restrict__ bo,
                           float* __restrict__ out) {
    __shared__ float sred[4][64];
    __shared__ float sfp[64], stg[64], red[128];
    const int g = blockIdx.x;
    const int t = threadIdx.x;
    const int c   = t & 63;
    const int row = t >> 6;

    int lo, hi;
    {
        int a = 0, b = nf;
        while (a < b) { int m2 = (a + b) >> 1; if (flag[m2] < g) a = m2 + 1; else b = m2; }
        lo = a;
        a = lo; b = nf;
        while (a < b) { int m2 = (a + b) >> 1; if (flag[m2] < g + 1) a = m2 + 1; else b = m2; }
        hi = a;
    }
    int dv = dvi[g];

    gdep_sync();

    float acc = 0.f;
    for (int i = lo + row; i < hi; i += 4)
        acc += g_featA[fidx[i] * 64 + c];
    sred[row][c] = acc;
    __syncthreads();
    if (t < 64) {
        sfp[t] = sred[0][t] + sred[1][t] + sred[2][t] + sred[3][t];
        stg[t] = g_featA[dv * 64 + t];
    }
    __syncthreads();
    if (t < 128) {
        float a2 = 0.f;
        if (t < 64) {
#pragma unroll
            for (int k = 0; k < 64; k++) a2 += sfp[k] * Wp[k * 64 + t];
        } else {
            int cc = t - 64;
#pragma unroll
            for (int k = 0; k < 64; k++) a2 += stg[k] * Wt[k * 64 + cc];
        }
        red[t] = eluf(a2) * Wo[t];
    }
    __syncthreads();
    for (int s2 = 64; s2 > 0; s2 >>= 1) {
        if (t < s2) red[t] += red[t + s2];
        __syncthreads();
    }
    if (t == 0) out[g] = red[0] + bo[0];
}

// ---------------------------------------------------------------------------
template <typename K, typename... Args>
static inline void launch_pdl(K kernel, int grid, int block, Args... args) {
    cudaLaunchConfig_t cfg = {};
    cfg.gridDim  = dim3(grid, 1, 1);
    cfg.blockDim = dim3(block, 1, 1);
    cfg.stream   = 0;
    cudaLaunchAttribute attr[1];
    attr[0].id = cudaLaunchAttributeProgrammaticStreamSerialization;
    attr[0].val.programmaticStreamSerializationAllowed = 1;
    cfg.attrs = attr;
    cfg.numAttrs = 1;
    cudaLaunchKernelEx(&cfg, kernel, args...);
}

// ---------------------------------------------------------------------------
extern "C" void kernel_launch(void* const* d_in, const int* in_sizes, int n_in,
                              void* d_out, int out_size) {
    const float* x     = (const float*)d_in[0];
    const int*   ei    = (const int*)  d_in[1];
    const int*   fidx  = (const int*)  d_in[2];
    const int*   flag  = (const int*)  d_in[3];
    const int*   dvi   = (const int*)  d_in[4];
    const float* W1    = (const float*)d_in[5];
    const float* as1   = (const float*)d_in[6];
    const float* ad1   = (const float*)d_in[7];
    const float* b1    = (const float*)d_in[8];
    const float* W2    = (const float*)d_in[9];
    const float* as2   = (const float*)d_in[10];
    const float* ad2   = (const float*)d_in[11];
    const float* b2    = (const float*)d_in[12];
    const float* W3    = (const float*)d_in[13];
    const float* as3   = (const float*)d_in[14];
    const float* ad3   = (const float*)d_in[15];
    const float* b3    = (const float*)d_in[16];
    const float* W4    = (const float*)d_in[17];
    const float* as4   = (const float*)d_in[18];
    const float* ad4   = (const float*)d_in[19];
    const float* b4    = (const float*)d_in[20];
    const float* Wp    = (const float*)d_in[21];
    const float* Wt    = (const float*)d_in[22];
    const float* Wo    = (const float*)d_in[23];
    const float* bo    = (const float*)d_in[24];
    float* out = (float*)d_out;

    const int nf  = in_sizes[2];                     // 8000
    const int AB8 = NNODES / 4 / 8;                  // 625, exact
    const int AB4 = (NNODES * 32 + 255) / 256;       // 2500

    static cudaStream_t s2 = nullptr;
    static cudaEvent_t evFork = nullptr, evJoin = nullptr;
    if (s2 == nullptr) {
        cudaStreamCreateWithFlags(&s2, cudaStreamNonBlocking);
        cudaEventCreateWithFlags(&evFork, cudaEventDisableTiming);
        cudaEventCreateWithFlags(&evJoin, cudaEventDisableTiming);
    }

    // ---- Fork: CSR build on s2, transform1 on main ----
    cudaEventRecord(evFork, 0);
    cudaStreamWaitEvent(s2, evFork, 0);
    k_count<<<CSR_BLKS, 256, 0, s2>>>(ei);
    k_scan<<<1, SCAN_T, 0, s2>>>();
    k_fill<<<CSR_BLKS, 256, 0, s2>>>(ei);
    cudaEventRecord(evJoin, s2);

    k_transform1<<<1250, 256>>>(x, W1, as1, ad1);

    cudaStreamWaitEvent(0, evJoin, 0);

    // ---- Layers: fused agg+transform for L1->L2, L2->L3 ----
    k_agg8f<false, false><<<AB8, 256>>>(b1, W2, as2, ad2);   // A -> B
    launch_pdl(k_agg8f<true, true>, AB8, 256, b2, W3, as3, ad3);  // B -> A
    launch_pdl(k_agg8, AB8, 256, b3);                        // A -> featA
    launch_pdl(k_transform4, 1250, 256, W4, as4, ad4);
    launch_pdl(k_agg4, AB4, 256, b4);
    launch_pdl(k_poolhead, NG, 256, fidx, flag, nf, dvi, Wp, Wt, Wo, bo, out);
}

// round 16
// speedup vs baseline: 1.0512x; 1.0512x over previous
#include <cuda_runtime.h>
#include <cuda_fp16.h>
#include <math.h>

// ---------------------------------------------------------------------------
// GATNet: 4x GATConv + pool + MLP head.  (R14 structure = best at 187.6us)
// R16: k_agg4 edge list split across TWO warps per node (interleaved),
// partials combined via smem.  Everything else identical to R14.
// ---------------------------------------------------------------------------

#define NNODES 20000
#define E0     320000
#define ETOT   (E0 + NNODES)
#define NG     8
#define SCAN_T 1024
#define SCAN_CHUNK ((NNODES + SCAN_T - 1) / SCAN_T)

__device__ __align__(16) float  g_featA[NNODES * 64];
__device__ __align__(16) __half g_featT[NNODES * 64];
__device__ __align__(16) __half g_ft4  [NNODES * 256];
__device__ __align__(16) float  g_asrc [NNODES * 8];
__device__ __align__(16) float  g_adst [NNODES * 8];
__device__ int g_cnt[NNODES];
__device__ int g_rowstart[NNODES + 1];
__device__ int g_cursor[NNODES];
__device__ int g_col[ETOT];

__device__ __forceinline__ float leaky02(float v) { return fmaxf(v, 0.2f * v); }
__device__ __forceinline__ float eluf(float v)    { return v > 0.f ? v : (__expf(v) - 1.f); }
__device__ __forceinline__ void gdep_sync() {
#if __CUDA_ARCH__ >= 900
    cudaGridDependencySynchronize();
#endif
}

// ---------------------------------------------------------------------------
// CSR build: 4 edges per thread.
// ---------------------------------------------------------------------------
#define CSR_BLKS 334
#define CSR_STRIDE (CSR_BLKS * 256)

__global__ void k_count(const int* __restrict__ ei) {
    int gtid = blockIdx.x * blockDim.x + threadIdx.x;
    int dd[4]; bool ok[4];
#pragma unroll
    for (int k = 0; k < 4; k++) {
        int e = gtid + k * CSR_STRIDE;
        ok[k] = (e < ETOT);
        dd[k] = ok[k] ? ((e < E0) ? ei[E0 + e] : (e - E0)) : 0;
    }
#pragma unroll
    for (int k = 0; k < 4; k++)
        if (ok[k]) atomicAdd(&g_cnt[dd[k]], 1);
}
__global__ void k_scan() {
    __shared__ int sp[SCAN_T];
    int t = threadIdx.x;
    int b0 = t * SCAN_CHUNK;
    int b1 = min(b0 + SCAN_CHUNK, NNODES);
    int sum = 0;
    for (int i = b0; i < b1; i++) sum += g_cnt[i];
    sp[t] = sum;
    __syncthreads();
    for (int off = 1; off < SCAN_T; off <<= 1) {
        int v = (t >= off) ? sp[t - off] : 0;
        __syncthreads();
        sp[t] += v;
        __syncthreads();
    }
    int base = (t == 0) ? 0 : sp[t - 1];
    for (int i = b0; i < b1; i++) {
        g_rowstart[i] = base;
        g_cursor[i]   = base;
        base += g_cnt[i];
    }
    if (t == SCAN_T - 1) g_rowstart[NNODES] = base;
}
__global__ void k_fill(const int* __restrict__ ei) {
    int gtid = blockIdx.x * blockDim.x + threadIdx.x;
    if (gtid < NNODES) g_cnt[gtid] = 0;
    int ss[4], dd[4]; bool ok[4];
#pragma unroll
    for (int k = 0; k < 4; k++) {
        int e = gtid + k * CSR_STRIDE;
        ok[k] = (e < ETOT);
        if (ok[k]) {
            if (e < E0) { ss[k] = ei[e]; dd[k] = ei[E0 + e]; }
            else        { ss[k] = e - E0; dd[k] = e - E0; }
        }
    }
#pragma unroll
    for (int k = 0; k < 4; k++) {
        if (ok[k]) {
            int pos = atomicAdd(&g_cursor[dd[k]], 1);
            g_col[pos] = ss[k];
        }
    }
}

// ---------------------------------------------------------------------------
// Transform layers 1-3 (D=64).  16 nodes/block, W staged in smem.
// ---------------------------------------------------------------------------
template<int IN, bool USE_G, bool PDL>
__global__ void k_transform64(const float* __restrict__ xin,
                              const float* __restrict__ W,
                              const float* __restrict__ a_src,
                              const float* __restrict__ a_dst) {
    constexpr int D = 64, H = 8, C = 8, NPB = 16;
    __shared__ __align__(16) float sW[IN * D];
    __shared__ __align__(16) float sx[NPB][IN];
    __shared__ __align__(16) float sh[NPB][D];
    const int t  = threadIdx.x;
    const int li = t / 16;
    const int q  = t % 16;
    const float* __restrict__ xp = USE_G ? (const float*)g_featA : xin;

    for (int i = t; i < IN * D / 4; i += 256)
        ((float4*)sW)[i] = ((const float4*)W)[i];

    if (PDL) gdep_sync();

    const int tile = blockIdx.x;               // grid = 1250
    for (int i = t; i < NPB * IN; i += 256) {
        int nn = tile * NPB + i / IN;
        sx[i / IN][i % IN] = xp[nn * IN + i % IN];
    }
    __syncthreads();

    const int n = tile * NPB + li;
    float4 acc = make_float4(0.f, 0.f, 0.f, 0.f);
#pragma unroll
    for (int i = 0; i < IN; i++) {
        float xv = sx[li][i];
        float4 w4 = *(const float4*)&sW[i * D + 4 * q];
        acc.x += xv * w4.x; acc.y += xv * w4.y;
        acc.z += xv * w4.z; acc.w += xv * w4.w;
    }
    {
        __half2* dst = (__half2*)&g_featT[n * D + 4 * q];
        dst[0] = __floats2half2_rn(acc.x, acc.y);
        dst[1] = __floats2half2_rn(acc.z, acc.w);
        *(float4*)&sh[li][4 * q] = acc;
    }
    __syncthreads();

    if (t < NPB * H) {
        int ln = t / H, h = t % H;
        int nn = tile * NPB + ln;
        float as = 0.f, ad = 0.f;
#pragma unroll
        for (int c = 0; c < C; c++) {
            float hv = sh[ln][h * C + c];
            as += hv * a_src[h * C + c];
            ad += hv * a_dst[h * C + c];
        }
        g_asrc[nn * H + h] = as;
        g_adst[nn * H + h] = ad;
    }
}

// ---------------------------------------------------------------------------
// Layer-4 transform (64 -> 256): 16 nodes/tile, 4 nodes per thread.
// ---------------------------------------------------------------------------
__global__ void k_transform4(const float* __restrict__ W,
                             const float* __restrict__ a_src,
                             const float* __restrict__ a_dst) {
    constexpr int NPB = 16;
    __shared__ __align__(16) float sx[NPB][64];
    __shared__ __align__(16) float sh[NPB][256];
    const int t = threadIdx.x;
    const int q = t & 63;
    const int m = t >> 6;
    const int h  = q >> 4;
    const int p0 = (2 * q) & 31;
    __half2* __restrict__ f4 = (__half2*)g_ft4;

    gdep_sync();

    const int tile = blockIdx.x;                   // grid = 1250
    for (int i = t; i < NPB * 64; i += 256) {
        int nn = tile * NPB + (i >> 6);
        sx[i >> 6][i & 63] = g_featA[nn * 64 + (i & 63)];
    }
    __syncthreads();

    float4 acc0 = make_float4(0.f,0.f,0.f,0.f);
    float4 acc1 = make_float4(0.f,0.f,0.f,0.f);
    float4 acc2 = make_float4(0.f,0.f,0.f,0.f);
    float4 acc3 = make_float4(0.f,0.f,0.f,0.f);
#pragma unroll 4
    for (int k = 0; k < 64; k++) {
        float4 w4 = __ldg((const float4*)&W[k * 256 + 4 * q]);
        float x0 = sx[m * 4 + 0][k];
        float x1 = sx[m * 4 + 1][k];
        float x2 = sx[m * 4 + 2][k];
        float x3 = sx[m * 4 + 3][k];
        acc0.x += x0*w4.x; acc0.y += x0*w4.y; acc0.z += x0*w4.z; acc0.w += x0*w4.w;
        acc1.x += x1*w4.x; acc1.y += x1*w4.y; acc1.z += x1*w4.z; acc1.w += x1*w4.w;
        acc2.x += x2*w4.x; acc2.y += x2*w4.y; acc2.z += x2*w4.z; acc2.w += x2*w4.w;
        acc3.x += x3*w4.x; acc3.y += x3*w4.y; acc3.z += x3*w4.z; acc3.w += x3*w4.w;
    }
    float4 accs[4] = {acc0, acc1, acc2, acc3};
#pragma unroll
    for (int i = 0; i < 4; i++) {
        int nl = m * 4 + i;
        int n  = tile * NPB + nl;
        f4[n * 128 + p0 * 4 + h]       = __floats2half2_rn(accs[i].x, accs[i].y);
        f4[n * 128 + (p0 + 1) * 4 + h] = __floats2half2_rn(accs[i].z, accs[i].w);
        *(float4*)&sh[nl][4 * q] = accs[i];
    }
    __syncthreads();

    if (t < NPB * 4) {                         // 16 nodes x 4 heads
        int nl = t >> 2, hh = t & 3;
        int nn = tile * NPB + nl;
        float as = 0.f, ad = 0.f;
#pragma unroll 8
        for (int c = 0; c < 64; c++) {
            float hv = sh[nl][hh * 64 + c];
            as += hv * a_src[hh * 64 + c];
            ad += hv * a_dst[hh * 64 + c];
        }
        g_asrc[nn * 4 + hh] = as;
        g_adst[nn * 4 + hh] = ad;
    }
}

// ---------------------------------------------------------------------------
// Aggregation, concat layers: FOUR nodes per warp, lane = 8*ni + h.
// ---------------------------------------------------------------------------
template<bool PDL>
__global__ void k_agg8(const float* __restrict__ bias) {
    int gw   = (blockIdx.x * blockDim.x + threadIdx.x) >> 5;
    int lane = threadIdx.x & 31;
    const int ni = lane >> 3;
    const int h  = lane & 7;
    const int d  = 4 * gw + ni;
    float4 b0 = *(const float4*)&bias[8 * h];
    float4 b1 = *(const float4*)&bias[8 * h + 4];

    if (PDL) gdep_sync();
    if (d >= NNODES) return;

    const float adv = g_adst[d * 8 + h];
    const int r0 = g_rowstart[d];
    const int r1 = g_rowstart[d + 1];
    const uint4* __restrict__ ftp = (const uint4*)g_featT;

    float den = 0.f;
    float a0 = 0.f, a1 = 0.f, a2 = 0.f, a3 = 0.f;
    float a4 = 0.f, a5 = 0.f, a6 = 0.f, a7 = 0.f;
#pragma unroll 4
    for (int j = r0; j < r1; j++) {
        int s = g_col[j];
        float e = __expf(leaky02(g_asrc[s * 8 + h] + adv));
        den += e;
        uint4 raw = __ldg(&ftp[s * 8 + h]);
        float2 f0 = __half22float2(*(const __half2*)&raw.x);
        float2 f1 = __half22float2(*(const __half2*)&raw.y);
        float2 f2 = __half22float2(*(const __half2*)&raw.z);
        float2 f3 = __half22float2(*(const __half2*)&raw.w);
        a0 += e * f0.x; a1 += e * f0.y;
        a2 += e * f1.x; a3 += e * f1.y;
        a4 += e * f2.x; a5 += e * f2.y;
        a6 += e * f3.x; a7 += e * f3.y;
    }
    float inv = 1.f / den;
    float4 o0, o1;
    o0.x = eluf(a0 * inv + b0.x);
    o0.y = eluf(a1 * inv + b0.y);
    o0.z = eluf(a2 * inv + b0.z);
    o0.w = eluf(a3 * inv + b0.w);
    o1.x = eluf(a4 * inv + b1.x);
    o1.y = eluf(a5 * inv + b1.y);
    o1.z = eluf(a6 * inv + b1.z);
    o1.w = eluf(a7 * inv + b1.w);
    *(float4*)&g_featA[d * 64 + 8 * h]     = o0;
    *(float4*)&g_featA[d * 64 + 8 * h + 4] = o1;
}

// ---------------------------------------------------------------------------
// Aggregation, layer 4: TWO warps per node (interleaved edge split), smem
// combine.  Block = 256 threads = 8 warps = 4 nodes.  Grid = 5000 exact.
// Lane owns channel pair (2L,2L+1); one 16B gather = all 4 heads.
// ---------------------------------------------------------------------------
__global__ void k_agg4(const float* __restrict__ bias) {
    __shared__ float scomb[4][32][12];
    const int t    = threadIdx.x;
    const int lane = t & 31;
    const int wInB = t >> 5;            // 0..7
    const int pid  = wInB >> 1;         // node slot 0..3
    const int half = wInB & 1;
    const int d    = blockIdx.x * 4 + pid;     // grid 5000 * 4 = 20000 exact
    const int hm   = lane & 3;
    float2 b = *(const float2*)&bias[2 * lane];

    gdep_sync();

    const float adv_m = g_adst[d * 4 + hm];
    const int r0 = g_rowstart[d];
    const int r1 = g_rowstart[d + 1];
    const uint4* __restrict__ ftp = (const uint4*)g_ft4;

    float den[4] = {0.f, 0.f, 0.f, 0.f};
    float ax[4]  = {0.f, 0.f, 0.f, 0.f};
    float ay[4]  = {0.f, 0.f, 0.f, 0.f};
#pragma unroll 2
    for (int j = r0 + half; j < r1; j += 2) {
        int s = g_col[j];
        float em = __expf(leaky02(g_asrc[s * 4 + hm] + adv_m));
        float ev0 = __shfl_sync(0xffffffff, em, 0, 4);
        float ev1 = __shfl_sync(0xffffffff, em, 1, 4);
        float ev2 = __shfl_sync(0xffffffff, em, 2, 4);
        float ev3 = __shfl_sync(0xffffffff, em, 3, 4);
        uint4 raw = __ldg(&ftp[s * 32 + lane]);
        float2 f0 = __half22float2(*(const __half2*)&raw.x);
        float2 f1 = __half22float2(*(const __half2*)&raw.y);
        float2 f2 = __half22float2(*(const __half2*)&raw.z);
        float2 f3 = __half22float2(*(const __half2*)&raw.w);
        den[0] += ev0; ax[0] += ev0 * f0.x; ay[0] += ev0 * f0.y;
        den[1] += ev1; ax[1] += ev1 * f1.x; ay[1] += ev1 * f1.y;
        den[2] += ev2; ax[2] += ev2 * f2.x; ay[2] += ev2 * f2.y;
        den[3] += ev3; ax[3] += ev3 * f3.x; ay[3] += ev3 * f3.y;
    }

    // combine halves through smem
    if (half == 1) {
        float* p = scomb[pid][lane];
#pragma unroll
        for (int k = 0; k < 4; k++) { p[k] = den[k]; p[4 + k] = ax[k]; p[8 + k] = ay[k]; }
    }
    __syncthreads();
    if (half == 0) {
        float* p = scomb[pid][lane];
#pragma unroll
        for (int k = 0; k < 4; k++) { den[k] += p[k]; ax[k] += p[4 + k]; ay[k] += p[8 + k]; }
        float v1 = 0.f, v2 = 0.f;
#pragma unroll
        for (int hh = 0; hh < 4; hh++) {
            float inv = 1.f / den[hh];
            v1 += ax[hh] * inv;
            v2 += ay[hh] * inv;
        }
        float2 o;
        o.x = eluf(0.25f * v1 + b.x);
        o.y = eluf(0.25f * v2 + b.y);
        *(float2*)&g_featA[d * 64 + 2 * lane] = o;
    }
}

// ---------------------------------------------------------------------------
// Fused pool+head (8 blocks).
// ---------------------------------------------------------------------------
__global__ void k_poolhead(const int* __restrict__ fidx, const int* __restrict__ flag,
                           int nf,
                           const int* __restrict__ dvi,
                           const float* __restrict__ Wp,
                           const float* __restrict__ Wt,
                           const float* __restrict__ Wo,
                           const float* __restrict__ bo,
                           float* __restrict__ out) {
    __shared__ float sred[4][64];
    __shared__ float sfp[64], stg[64], red[128];
    const int g = blockIdx.x;
    const int t = threadIdx.x;
    const int c   = t & 63;
    const int row = t >> 6;

    int lo, hi;
    {
        int a = 0, b = nf;
        while (a < b) { int m2 = (a + b) >> 1; if (flag[m2] < g) a = m2 + 1; else b = m2; }
        lo = a;
        a = lo; b = nf;
        while (a < b) { int m2 = (a + b) >> 1; if (flag[m2] < g + 1) a = m2 + 1; else b = m2; }
        hi = a;
    }
    int dv = dvi[g];

    gdep_sync();

    float acc = 0.f;
    for (int i = lo + row; i < hi; i += 4)
        acc += g_featA[fidx[i] * 64 + c];
    sred[row][c] = acc;
    __syncthreads();
    if (t < 64) {
        sfp[t] = sred[0][t] + sred[1][t] + sred[2][t] + sred[3][t];
        stg[t] = g_featA[dv * 64 + t];
    }
    __syncthreads();
    if (t < 128) {
        float a2 = 0.f;
        if (t < 64) {
#pragma unroll
            for (int k = 0; k < 64; k++) a2 += sfp[k] * Wp[k * 64 + t];
        } else {
            int cc = t - 64;
#pragma unroll
            for (int k = 0; k < 64; k++) a2 += stg[k] * Wt[k * 64 + cc];
        }
        red[t] = eluf(a2) * Wo[t];
    }
    __syncthreads();
    for (int s2 = 64; s2 > 0; s2 >>= 1) {
        if (t < s2) red[t] += red[t + s2];
        __syncthreads();
    }
    if (t == 0) out[g] = red[0] + bo[0];
}

// ---------------------------------------------------------------------------
template <typename K, typename... Args>
static inline void launch_pdl(K kernel, int grid, int block, Args... args) {
    cudaLaunchConfig_t cfg = {};
    cfg.gridDim  = dim3(grid, 1, 1);
    cfg.blockDim = dim3(block, 1, 1);
    cfg.stream   = 0;
    cudaLaunchAttribute attr[1];
    attr[0].id = cudaLaunchAttributeProgrammaticStreamSerialization;
    attr[0].val.programmaticStreamSerializationAllowed = 1;
    cfg.attrs = attr;
    cfg.numAttrs = 1;
    cudaLaunchKernelEx(&cfg, kernel, args...);
}

// ---------------------------------------------------------------------------
extern "C" void kernel_launch(void* const* d_in, const int* in_sizes, int n_in,
                              void* d_out, int out_size) {
    const float* x     = (const float*)d_in[0];
    const int*   ei    = (const int*)  d_in[1];
    const int*   fidx  = (const int*)  d_in[2];
    const int*   flag  = (const int*)  d_in[3];
    const int*   dvi   = (const int*)  d_in[4];
    const float* W1    = (const float*)d_in[5];
    const float* as1   = (const float*)d_in[6];
    const float* ad1   = (const float*)d_in[7];
    const float* b1    = (const float*)d_in[8];
    const float* W2    = (const float*)d_in[9];
    const float* as2   = (const float*)d_in[10];
    const float* ad2   = (const float*)d_in[11];
    const float* b2    = (const float*)d_in[12];
    const float* W3    = (const float*)d_in[13];
    const float* as3   = (const float*)d_in[14];
    const float* ad3   = (const float*)d_in[15];
    const float* b3    = (const float*)d_in[16];
    const float* W4    = (const float*)d_in[17];
    const float* as4   = (const float*)d_in[18];
    const float* ad4   = (const float*)d_in[19];
    const float* b4    = (const float*)d_in[20];
    const float* Wp    = (const float*)d_in[21];
    const float* Wt    = (const float*)d_in[22];
    const float* Wo    = (const float*)d_in[23];
    const float* bo    = (const float*)d_in[24];
    float* out = (float*)d_out;

    const int nf  = in_sizes[2];                     // 8000
    const int AB8 = (NNODES / 4 * 32 + 255) / 256;   // 625
    const int AB4 = NNODES / 4;                      // 5000 (2 warps/node)

    static cudaStream_t s2 = nullptr;
    static cudaEvent_t evFork = nullptr, evJoin = nullptr;
    if (s2 == nullptr) {
        cudaStreamCreateWithFlags(&s2, cudaStreamNonBlocking);
        cudaEventCreateWithFlags(&evFork, cudaEventDisableTiming);
        cudaEventCreateWithFlags(&evJoin, cudaEventDisableTiming);
    }

    // ---- Fork: CSR build on s2, transform1 on main ----
    cudaEventRecord(evFork, 0);
    cudaStreamWaitEvent(s2, evFork, 0);
    k_count<<<CSR_BLKS, 256, 0, s2>>>(ei);
    k_scan<<<1, SCAN_T, 0, s2>>>();
    k_fill<<<CSR_BLKS, 256, 0, s2>>>(ei);
    cudaEventRecord(evJoin, s2);

    k_transform64<16, false, false><<<1250, 256>>>(x, W1, as1, ad1);

    cudaStreamWaitEvent(0, evJoin, 0);

    // ---- Layer chain with PDL overlap ----
    k_agg8<false><<<AB8, 256>>>(b1);
    launch_pdl(k_transform64<64, true, true>, 1250, 256, (const float*)nullptr, W2, as2, ad2);
    launch_pdl(k_agg8<true>, AB8, 256, b2);
    launch_pdl(k_transform64<64, true, true>, 1250, 256, (const float*)nullptr, W3, as3, ad3);
    launch_pdl(k_agg8<true>, AB8, 256, b3);
    launch_pdl(k_transform4, 1250, 256, W4, as4, ad4);
    launch_pdl(k_agg4, AB4, 256, b4);
    launch_pdl(k_poolhead, NG, 256, fidx, flag, nf, dvi, Wp, Wt, Wo, bo, out);
}